// round 7
// baseline (speedup 1.0000x reference)
#include <cuda_runtime.h>

#define B_SZ 65536
#define D_SZ 512
#define V4_PER_ROW (D_SZ / 4)              // 128
#define TOTAL_V4 (B_SZ * V4_PER_ROW)       // 8,388,608
#define NC 16
#define NBLOCKS 2048
#define NTHREADS 256
#define WARPS_PER_BLOCK (NTHREADS / 32)    // 8
#define GRID_STRIDE (NBLOCKS * NTHREADS)   // 524,288 -> exactly 16 iters/thread
#define ITERS (TOTAL_V4 / GRID_STRIDE)     // 16
#define MLP 8
#define NPAIR (NC * (NC - 1) / 2)          // 120
#define PAIRS_PER_WARP (NPAIR / WARPS_PER_BLOCK)  // 15

__device__ float g_partials[NBLOCKS];
__device__ unsigned int g_ticket = 0;      // atomicInc wraps to 0 -> graph-replay safe

__global__ __launch_bounds__(NTHREADS) void k_island_fused(
    const float4* __restrict__ x,
    const int* __restrict__ y,             // int32 (JAX x64 disabled)
    const float4* __restrict__ centers,
    float* __restrict__ out)
{
    __shared__ float ws[WARPS_PER_BLOCK];
    __shared__ float norms[NC];
    __shared__ float warp_pair[WARPS_PER_BLOCK];
    __shared__ unsigned int s_ticket;

    const int t = threadIdx.x;
    const int lane = t & 31;
    const int wid = t >> 5;
    const int base = blockIdx.x * NTHREADS + t;

    // ---- Phase 1: streaming center-loss partial ----
    // Centers read through L1 (32KB, fully resident); 8 front-batched
    // independent LDG.128 of x per body for deep MLP.
    float a0 = 0.f, a1 = 0.f, a2 = 0.f, a3 = 0.f;

    #pragma unroll
    for (int outer = 0; outer < ITERS / MLP; outer++) {
        float4 xv[MLP];
        #pragma unroll
        for (int u = 0; u < MLP; u++)
            xv[u] = __ldg(&x[base + (outer * MLP + u) * GRID_STRIDE]);
        #pragma unroll
        for (int u = 0; u < MLP; u++) {
            const int idx = base + (outer * MLP + u) * GRID_STRIDE;
            const int cls = __ldg(&y[idx >> 7]) & 15;          // L1-hot broadcast
            const float4 cv = __ldg(&centers[(cls << 7) + (idx & 127)]); // L1-hot 512B
            float d;
            d = xv[u].x - cv.x; a0 = fmaf(d, d, a0);
            d = xv[u].y - cv.y; a1 = fmaf(d, d, a1);
            d = xv[u].z - cv.z; a2 = fmaf(d, d, a2);
            d = xv[u].w - cv.w; a3 = fmaf(d, d, a3);
        }
    }
    float acc = (a0 + a1) + (a2 + a3);

    #pragma unroll
    for (int o = 16; o > 0; o >>= 1)
        acc += __shfl_down_sync(0xffffffffu, acc, o);
    if (lane == 0) ws[wid] = acc;
    __syncthreads();
    if (t == 0) {
        float v = 0.f;
        #pragma unroll
        for (int w = 0; w < WARPS_PER_BLOCK; w++) v += ws[w];
        g_partials[blockIdx.x] = v;
        __threadfence();
        s_ticket = atomicInc(&g_ticket, NBLOCKS - 1);
    }
    __syncthreads();
    if (s_ticket != NBLOCKS - 1)
        return;                                       // not the last block

    // ---- Phase 2 (last block only): final reduce + island term ----
    // Partials (2048 floats, L2-hot): strided per-thread then shuffle; fixed order.
    float s = 0.0f;
    #pragma unroll
    for (int i = 0; i < NBLOCKS / NTHREADS; i++)
        s += g_partials[i * NTHREADS + t];
    #pragma unroll
    for (int o = 16; o > 0; o >>= 1)
        s += __shfl_down_sync(0xffffffffu, s, o);
    if (lane == 0) ws[wid] = s;

    // Norms: warp-per-2-rows, centers via L1/L2 (hot)
    #pragma unroll
    for (int r = 0; r < 2; r++) {
        const int row = wid * 2 + r;
        float ns = 0.0f;
        #pragma unroll
        for (int i = 0; i < 4; i++) {
            float4 v = __ldg(&centers[(row << 7) + i * 32 + lane]);
            ns += v.x * v.x + v.y * v.y + v.z * v.z + v.w * v.w;
        }
        #pragma unroll
        for (int o = 16; o > 0; o >>= 1)
            ns += __shfl_down_sync(0xffffffffu, ns, o);
        if (lane == 0) norms[row] = sqrtf(ns);
    }
    __syncthreads();

    // Pairs: 15 per warp, fixed order
    float psum = 0.0f;
    #pragma unroll
    for (int pp = 0; pp < PAIRS_PER_WARP; pp++) {
        const int p = wid * PAIRS_PER_WARP + pp;
        int j = 0, rem = p;
        while (rem >= NC - 1 - j) { rem -= NC - 1 - j; j++; }
        const int k = j + 1 + rem;
        float dot = 0.0f;
        #pragma unroll
        for (int i = 0; i < 4; i++) {
            float4 a = __ldg(&centers[(j << 7) + i * 32 + lane]);
            float4 b = __ldg(&centers[(k << 7) + i * 32 + lane]);
            dot += a.x * b.x + a.y * b.y + a.z * b.z + a.w * b.w;
        }
        #pragma unroll
        for (int o = 16; o > 0; o >>= 1)
            dot += __shfl_down_sync(0xffffffffu, dot, o);
        if (lane == 0)
            psum += dot / (norms[j] * norms[k] + 1e-9f) + 1.0f;
    }
    if (lane == 0) warp_pair[wid] = psum;
    __syncthreads();

    if (t == 0) {
        float total = 0.0f;
        float island = 0.0f;
        #pragma unroll
        for (int w = 0; w < WARPS_PER_BLOCK; w++) {
            total += ws[w];
            island += warp_pair[w];
        }
        // SCALE = 1, LAMDA = 1, LAMDA1 = 10
        float loss_center = 0.5f * total * (1.0f / (float)B_SZ);
        out[0] = loss_center + 10.0f * island;
    }
}

extern "C" void kernel_launch(void* const* d_in, const int* in_sizes, int n_in,
                              void* d_out, int out_size)
{
    // Identify inputs by element count (robust to ordering):
    //   output_features: 65536*512 = 33554432
    //   y_truth:         65536
    //   feature_centers: 16*512   = 8192
    const float4* x = nullptr;
    const int* y = nullptr;
    const float4* centers = nullptr;
    for (int i = 0; i < n_in; i++) {
        if (in_sizes[i] == 33554432)      x = (const float4*)d_in[i];
        else if (in_sizes[i] == 65536)    y = (const int*)d_in[i];
        else if (in_sizes[i] == 8192)     centers = (const float4*)d_in[i];
    }
    float* out = (float*)d_out;

    k_island_fused<<<NBLOCKS, NTHREADS>>>(x, y, centers, out);
}

// round 8
// speedup vs baseline: 1.2464x; 1.2464x over previous
#include <cuda_runtime.h>

#define B_SZ 65536
#define D_SZ 512
#define V4_PER_ROW (D_SZ / 4)              // 128
#define NC 16
#define NBLOCKS 2048
#define NTHREADS 256
#define WARPS_PER_BLOCK (NTHREADS / 32)    // 8
#define ROWS_PER_WARP 4                    // 2048*8*4 = 65536
#define NPAIR (NC * (NC - 1) / 2)          // 120
#define PAIRS_PER_WARP (NPAIR / WARPS_PER_BLOCK)  // 15

__device__ float g_partials[NBLOCKS];
__device__ unsigned int g_ticket = 0;      // atomicInc wraps to 0 -> graph-replay safe

__global__ __launch_bounds__(NTHREADS) void k_island_fused(
    const float4* __restrict__ x,
    const int* __restrict__ y,             // int32 (JAX x64 disabled)
    const float4* __restrict__ centers,
    float* __restrict__ out)
{
    __shared__ float4 sc[NC * V4_PER_ROW]; // 32 KB center cache (proven R3 config)
    __shared__ float ws[WARPS_PER_BLOCK];
    __shared__ float norms[NC];
    __shared__ float warp_pair[WARPS_PER_BLOCK];
    __shared__ unsigned int s_ticket;

    const int t = threadIdx.x;
    const int lane = t & 31;
    const int wid = t >> 5;

    #pragma unroll
    for (int i = 0; i < (NC * V4_PER_ROW) / NTHREADS; i++)
        sc[i * NTHREADS + t] = centers[i * NTHREADS + t];
    __syncthreads();

    // ---- Phase 1: EXACT R3 streaming body (measured 24.5us / 5.2 TB/s) ----
    const int gw = blockIdx.x * WARPS_PER_BLOCK + wid;

    float acc = 0.0f;
    #pragma unroll
    for (int r = 0; r < ROWS_PER_WARP; r++) {
        const int row = gw * ROWS_PER_WARP + r;
        const int cls = __ldg(&y[row]) & 15;          // broadcast load
        const float4* __restrict__ xr = x + (size_t)row * V4_PER_ROW;
        const float4* __restrict__ cr = sc + (cls << 7);
        #pragma unroll
        for (int i = 0; i < 4; i++) {
            float4 xv = __ldg(&xr[i * 32 + lane]);    // coalesced 512B
            float4 cv = cr[i * 32 + lane];            // conflict-free LDS.128
            float d0 = xv.x - cv.x;
            float d1 = xv.y - cv.y;
            float d2 = xv.z - cv.z;
            float d3 = xv.w - cv.w;
            acc = fmaf(d0, d0, acc);
            acc = fmaf(d1, d1, acc);
            acc = fmaf(d2, d2, acc);
            acc = fmaf(d3, d3, acc);
        }
    }

    #pragma unroll
    for (int o = 16; o > 0; o >>= 1)
        acc += __shfl_down_sync(0xffffffffu, acc, o);
    if (lane == 0) ws[wid] = acc;
    __syncthreads();
    if (t == 0) {
        float v = 0.f;
        #pragma unroll
        for (int w = 0; w < WARPS_PER_BLOCK; w++) v += ws[w];
        g_partials[blockIdx.x] = v;
        __threadfence();
        s_ticket = atomicInc(&g_ticket, NBLOCKS - 1);
    }
    __syncthreads();
    if (s_ticket != NBLOCKS - 1)
        return;                                       // not the last block

    // ---- Phase 2 (last block only): final reduce + island term ----
    // Partials (2048 floats, L2-hot): strided per-thread then shuffle; fixed order.
    float s = 0.0f;
    #pragma unroll
    for (int i = 0; i < NBLOCKS / NTHREADS; i++)
        s += g_partials[i * NTHREADS + t];
    #pragma unroll
    for (int o = 16; o > 0; o >>= 1)
        s += __shfl_down_sync(0xffffffffu, s, o);
    if (lane == 0) ws[wid] = s;

    // Norms: warp-per-2-rows (centers still resident in sc)
    #pragma unroll
    for (int r = 0; r < 2; r++) {
        const int row = wid * 2 + r;
        const float4* cr = sc + (row << 7);
        float ns = 0.0f;
        #pragma unroll
        for (int i = 0; i < 4; i++) {
            float4 v = cr[i * 32 + lane];
            ns += v.x * v.x + v.y * v.y + v.z * v.z + v.w * v.w;
        }
        #pragma unroll
        for (int o = 16; o > 0; o >>= 1)
            ns += __shfl_down_sync(0xffffffffu, ns, o);
        if (lane == 0) norms[row] = sqrtf(ns);
    }
    __syncthreads();

    // Pairs: 15 per warp, fixed order
    float psum = 0.0f;
    #pragma unroll
    for (int pp = 0; pp < PAIRS_PER_WARP; pp++) {
        const int p = wid * PAIRS_PER_WARP + pp;
        int j = 0, rem = p;
        while (rem >= NC - 1 - j) { rem -= NC - 1 - j; j++; }
        const int k = j + 1 + rem;
        const float4* cj = sc + (j << 7);
        const float4* ck = sc + (k << 7);
        float dot = 0.0f;
        #pragma unroll
        for (int i = 0; i < 4; i++) {
            float4 a = cj[i * 32 + lane];
            float4 b = ck[i * 32 + lane];
            dot += a.x * b.x + a.y * b.y + a.z * b.z + a.w * b.w;
        }
        #pragma unroll
        for (int o = 16; o > 0; o >>= 1)
            dot += __shfl_down_sync(0xffffffffu, dot, o);
        if (lane == 0)
            psum += dot / (norms[j] * norms[k] + 1e-9f) + 1.0f;
    }
    if (lane == 0) warp_pair[wid] = psum;
    __syncthreads();

    if (t == 0) {
        float total = 0.0f;
        float island = 0.0f;
        #pragma unroll
        for (int w = 0; w < WARPS_PER_BLOCK; w++) {
            total += ws[w];
            island += warp_pair[w];
        }
        // SCALE = 1, LAMDA = 1, LAMDA1 = 10
        float loss_center = 0.5f * total * (1.0f / (float)B_SZ);
        out[0] = loss_center + 10.0f * island;
    }
}

extern "C" void kernel_launch(void* const* d_in, const int* in_sizes, int n_in,
                              void* d_out, int out_size)
{
    // Identify inputs by element count (robust to ordering):
    //   output_features: 65536*512 = 33554432
    //   y_truth:         65536
    //   feature_centers: 16*512   = 8192
    const float4* x = nullptr;
    const int* y = nullptr;
    const float4* centers = nullptr;
    for (int i = 0; i < n_in; i++) {
        if (in_sizes[i] == 33554432)      x = (const float4*)d_in[i];
        else if (in_sizes[i] == 65536)    y = (const int*)d_in[i];
        else if (in_sizes[i] == 8192)     centers = (const float4*)d_in[i];
    }
    float* out = (float*)d_out;

    k_island_fused<<<NBLOCKS, NTHREADS>>>(x, y, centers, out);
}